// round 4
// baseline (speedup 1.0000x reference)
#include <cuda_runtime.h>
#include <cuda_bf16.h>
#include <stdint.h>

// Problem constants
#define BATCH 16
#define SEQ   4096
#define FEAT  512
#define MROWS (BATCH*SEQ)      // 65536
#define M_TILE 64
#define N_CHUNK 128
#define K_TILE 64
#define NUM_CTAS (MROWS / M_TILE)   // 1024
#define THREADS 256

#define XSTR 516   // 516 % 32 == 4 -> conflict-free fragment gathers
#define WSTR 132   // 132 % 32 == 4

// smem partition sizes (in 4-byte words)
#define XS_WORDS (M_TILE * XSTR)        // 33024
#define WS_WORDS (K_TILE * WSTR)        // 8448
#define US_WORDS FEAT
#define BS_WORDS FEAT
#define SB_WORDS (2 * M_TILE)
#define RD_WORDS M_TILE
#define SMEM_WORDS (XS_WORDS + WS_WORDS + US_WORDS + BS_WORDS + SB_WORDS + RD_WORDS)
#define SMEM_BYTES (SMEM_WORDS * 4)

// scratch
__device__ float g_e[MROWS];             // exp(scores)
__device__ float g_part[NUM_CTAS];       // per-CTA partial sum of e
__device__ float g_sumE[1];
#define SCHUNK 32
__device__ float g_po[BATCH * SCHUNK * FEAT];  // pooling partials

__device__ __forceinline__ uint32_t f2tf32(float x) {
    uint32_t r;
    asm("cvt.rna.tf32.f32 %0, %1;" : "=r"(r) : "f"(x));
    return r;
}

__device__ __forceinline__ void mma_tf32(float& d0, float& d1, float& d2, float& d3,
                                         uint32_t a0, uint32_t a1, uint32_t a2, uint32_t a3,
                                         uint32_t b0, uint32_t b1) {
    asm volatile(
        "mma.sync.aligned.m16n8k8.row.col.f32.tf32.tf32.f32 "
        "{%0,%1,%2,%3}, {%4,%5,%6,%7}, {%8,%9}, {%0,%1,%2,%3};"
        : "+f"(d0), "+f"(d1), "+f"(d2), "+f"(d3)
        : "r"(a0), "r"(a1), "r"(a2), "r"(a3), "r"(b0), "r"(b1));
}

// Kernel 1: per 64-row tile: h = tanh(x@W + b); score = h.u; e = exp(score);
// writes g_e[row] and per-CTA partial sum g_part[cta]. Deterministic.
__global__ __launch_bounds__(THREADS, 1)
void k1_gemm_score(const float* __restrict__ x, const float* __restrict__ Wg,
                   const float* __restrict__ bg, const float* __restrict__ ug) {
    extern __shared__ uint32_t smem[];
    uint32_t* xs = smem;                       // [M_TILE][XSTR] tf32 bits
    uint32_t* ws = xs + XS_WORDS;              // [K_TILE][WSTR] tf32 bits
    float* us = (float*)(ws + WS_WORDS);       // [FEAT]
    float* bs = us + US_WORDS;                 // [FEAT]
    float* sbuf = bs + BS_WORDS;               // [2][M_TILE]
    float* red  = sbuf + SB_WORDS;             // [M_TILE]

    const int tid = threadIdx.x;
    const int lane = tid & 31;
    const int wid = tid >> 5;
    const int wm = wid & 3;        // warp row group (16 rows each)
    const int wn = wid >> 2;       // warp col group (64 cols each)
    const int row0 = blockIdx.x * M_TILE;

    // load u, b
    #pragma unroll
    for (int i = 0; i < 2; i++) {
        int idx = tid + i * 256;
        us[idx] = ug[idx];
        bs[idx] = bg[idx];
    }
    // load x tile (64 x 512) -> tf32 smem, padded stride
    const float* xbase = x + (size_t)row0 * FEAT;
    #pragma unroll
    for (int i = 0; i < 32; i++) {
        int t = tid + i * 256;
        int r = t >> 7;             // 128 float4 per row
        int c = (t & 127) * 4;
        float4 v = *(const float4*)(xbase + (size_t)r * FEAT + c);
        uint32_t* dst = xs + r * XSTR + c;
        dst[0] = f2tf32(v.x); dst[1] = f2tf32(v.y);
        dst[2] = f2tf32(v.z); dst[3] = f2tf32(v.w);
    }

    float sp0 = 0.0f, sp1 = 0.0f;   // score partials for rows r0, r0+8

    const int lr = lane >> 2;       // 0..7
    const int lc = lane & 3;        // 0..3

    for (int nc = 0; nc < 4; nc++) {
        const int n0 = nc * N_CHUNK;
        float acc[8][4];
        #pragma unroll
        for (int nt = 0; nt < 8; nt++)
            acc[nt][0] = acc[nt][1] = acc[nt][2] = acc[nt][3] = 0.0f;

        for (int kt = 0; kt < 8; kt++) {
            __syncthreads();   // previous ws users done / x stores visible
            // load W tile [K_TILE x N_CHUNK] at (k0, n0)
            const int k0 = kt * K_TILE;
            #pragma unroll
            for (int i = 0; i < 8; i++) {
                int t = tid + i * 256;
                int kk = t >> 5;
                int nn = (t & 31) * 4;
                float4 v = *(const float4*)(Wg + (size_t)(k0 + kk) * FEAT + n0 + nn);
                uint32_t* dst = ws + kk * WSTR + nn;
                dst[0] = f2tf32(v.x); dst[1] = f2tf32(v.y);
                dst[2] = f2tf32(v.z); dst[3] = f2tf32(v.w);
            }
            __syncthreads();

            #pragma unroll
            for (int k8 = 0; k8 < 8; k8++) {
                const int kc = k0 + k8 * 8 + lc;
                const int ra = (wm * 16 + lr) * XSTR;
                uint32_t a0 = xs[ra + kc];
                uint32_t a1 = xs[ra + 8 * XSTR + kc];
                uint32_t a2 = xs[ra + kc + 4];
                uint32_t a3 = xs[ra + 8 * XSTR + kc + 4];
                const int kb = (k8 * 8 + lc) * WSTR;
                #pragma unroll
                for (int nt = 0; nt < 8; nt++) {
                    int nn = wn * 64 + nt * 8 + lr;
                    uint32_t b0 = ws[kb + nn];
                    uint32_t b1 = ws[kb + 4 * WSTR + nn];
                    mma_tf32(acc[nt][0], acc[nt][1], acc[nt][2], acc[nt][3],
                             a0, a1, a2, a3, b0, b1);
                }
            }
        }

        // epilogue for this n-chunk: tanh + dot with u (fp32)
        #pragma unroll
        for (int nt = 0; nt < 8; nt++) {
            int cb = n0 + wn * 64 + nt * 8 + lc * 2;
            float u0 = us[cb], u1 = us[cb + 1];
            float bb0 = bs[cb], bb1 = bs[cb + 1];
            float h;
            h = tanhf(acc[nt][0] + bb0); sp0 += h * u0;
            h = tanhf(acc[nt][1] + bb1); sp0 += h * u1;
            h = tanhf(acc[nt][2] + bb0); sp1 += h * u0;
            h = tanhf(acc[nt][3] + bb1); sp1 += h * u1;
        }
    }

    // reduce over the 4 lanes sharing a row (fixed order)
    sp0 += __shfl_xor_sync(0xffffffffu, sp0, 1);
    sp0 += __shfl_xor_sync(0xffffffffu, sp0, 2);
    sp1 += __shfl_xor_sync(0xffffffffu, sp1, 1);
    sp1 += __shfl_xor_sync(0xffffffffu, sp1, 2);
    __syncthreads();
    if ((lane & 3) == 0) {
        int r = wm * 16 + lr;
        sbuf[wn * M_TILE + r] = sp0;
        sbuf[wn * M_TILE + r + 8] = sp1;
    }
    __syncthreads();

    if (tid < M_TILE) {
        float s = sbuf[tid] + sbuf[M_TILE + tid];   // fixed combine order
        float e = expf(s);
        g_e[row0 + tid] = e;
        red[tid] = e;
    }
    __syncthreads();
    // fixed-order tree reduce of 64 values
    for (int off = 32; off > 0; off >>= 1) {
        if (tid < off) red[tid] += red[tid + off];
        __syncthreads();
    }
    if (tid == 0) g_part[blockIdx.x] = red[0];
}

// Kernel 2: deterministic reduce of 1024 CTA partials
__global__ void k2_reduce() {
    __shared__ float red[256];
    int tid = threadIdx.x;
    float v = g_part[tid] + g_part[tid + 256] + g_part[tid + 512] + g_part[tid + 768];
    red[tid] = v;
    __syncthreads();
    for (int off = 128; off > 0; off >>= 1) {
        if (tid < off) red[tid] += red[tid + off];
        __syncthreads();
    }
    if (tid == 0) g_sumE[0] = red[0];
}

// Kernel 3: pooling partials. grid (SCHUNK, BATCH), 256 threads, 2 feats/thread.
__global__ __launch_bounds__(256)
void k3_pool(const float* __restrict__ x) {
    int b = blockIdx.y;
    int ch = blockIdx.x;
    int tid = threadIdx.x;
    int f0 = tid, f1 = tid + 256;
    const int SPC = SEQ / SCHUNK;  // 128
    const float* xp = x + ((size_t)b * SEQ + (size_t)ch * SPC) * FEAT;
    const float* ep = g_e + b * SEQ + ch * SPC;
    float a0 = 0.0f, a1 = 0.0f;
    #pragma unroll 4
    for (int s = 0; s < SPC; s++) {
        float ev = ep[s];
        a0 += xp[(size_t)s * FEAT + f0] * ev;
        a1 += xp[(size_t)s * FEAT + f1] * ev;
    }
    float* po = g_po + ((size_t)b * SCHUNK + ch) * FEAT;
    po[f0] = a0;
    po[f1] = a1;
}

// Kernel 4: combine chunks, normalize. grid BATCH, 512 threads.
__global__ __launch_bounds__(512)
void k4_final(float* __restrict__ out) {
    int b = blockIdx.x;
    int f = threadIdx.x;
    float s = 0.0f;
    #pragma unroll
    for (int c = 0; c < SCHUNK; c++)
        s += g_po[((size_t)b * SCHUNK + c) * FEAT + f];
    float denom = g_sumE[0] + 1e-7f;
    out[b * FEAT + f] = s / denom;
}

extern "C" void kernel_launch(void* const* d_in, const int* in_sizes, int n_in,
                              void* d_out, int out_size) {
    const float* x = (const float*)d_in[0];
    const float* W = (const float*)d_in[1];
    const float* b = (const float*)d_in[2];
    const float* u = (const float*)d_in[3];
    float* out = (float*)d_out;

    cudaFuncSetAttribute(k1_gemm_score, cudaFuncAttributeMaxDynamicSharedMemorySize, SMEM_BYTES);

    k1_gemm_score<<<NUM_CTAS, THREADS, SMEM_BYTES>>>(x, W, b, u);
    k2_reduce<<<1, 256>>>();
    dim3 g3(SCHUNK, BATCH);
    k3_pool<<<g3, 256>>>(x);
    k4_final<<<BATCH, 512>>>(out);
}

// round 6
// speedup vs baseline: 1.6898x; 1.6898x over previous
#include <cuda_runtime.h>
#include <stdint.h>

// ---------------- problem constants ----------------
#define BATCH 16
#define SEQ   4096
#define FEAT  512
#define MROWS (BATCH*SEQ)          // 65536
#define M_CTA 128
#define NUM_CTAS (MROWS/M_CTA)     // 512
#define THREADS 512
#define NKT 16                     // K slices of 32
#define NC 2                       // N halves of 256

// A slice smem: 128 rows x (32+4 pad) words = 144B/row
#define ASTR 36
#define A_TILE_B (M_CTA*ASTR*4)    // 18432
#define B_TILE_B 32768             // 32 k x 256 n x 4B (fragment-major)

// smem layout (bytes)
#define OFF_U    0
#define OFF_BV   2048
#define OFF_SRED 4096              // 2*128 floats
#define OFF_SE   5120              // 128 floats
#define OFF_A0   5632
#define OFF_A1   (OFF_A0 + A_TILE_B)   // 24064
#define OFF_B0   (OFF_A1 + A_TILE_B)   // 42496
#define OFF_B1   (OFF_B0 + B_TILE_B)   // 75264
#define SMEM_TOTAL (OFF_B1 + B_TILE_B) // 108032

// ---------------- global scratch ----------------
__device__ float g_Wfrag[FEAT*FEAT];      // fragment-major, tf32(RNA) W
__device__ float g_part[NUM_CTAS];
__device__ float g_sumE;
__device__ float g_po[(size_t)NUM_CTAS*FEAT];

__device__ __forceinline__ uint32_t f2tf32(float x) {
    uint32_t r;
    asm("cvt.rna.tf32.f32 %0, %1;" : "=r"(r) : "f"(x));
    return r;
}

__device__ __forceinline__ void mma_tf32(float& d0, float& d1, float& d2, float& d3,
                                         uint32_t a0, uint32_t a1, uint32_t a2, uint32_t a3,
                                         uint32_t b0, uint32_t b1) {
    asm volatile(
        "mma.sync.aligned.m16n8k8.row.col.f32.tf32.tf32.f32 "
        "{%0,%1,%2,%3}, {%4,%5,%6,%7}, {%8,%9}, {%0,%1,%2,%3};"
        : "+f"(d0), "+f"(d1), "+f"(d2), "+f"(d3)
        : "r"(a0), "r"(a1), "r"(a2), "r"(a3), "r"(b0), "r"(b1));
}

__device__ __forceinline__ uint32_t smem_u32(const void* p) {
    uint32_t a;
    asm("{ .reg .u64 t; cvta.to.shared.u64 t, %1; cvt.u32.u64 %0, t; }" : "=r"(a) : "l"(p));
    return a;
}

__device__ __forceinline__ void cpa16(uint32_t dst, const void* src) {
    asm volatile("cp.async.cg.shared.global [%0], [%1], 16;" :: "r"(dst), "l"(src));
}

// fast tanh via 2 MUFU; rel err ~1e-6, saturates to +-1
__device__ __forceinline__ float ftanh(float v) {
    float t = __expf(2.0f * v);
    return 1.0f - __fdividef(2.0f, t + 1.0f);
}

// ---------------- k0: pack W -> fragment-major tf32 ----------------
// g index layout: [kt(16)][nc(2)][wn(2)][k8l(4)][ntp(8)][lane(32)] of float4
// float4 = ( W[k][n0], W[k+4][n0], W[k][n0+8], W[k+4][n0+8] ) as RNA tf32 bits
// k = kt*32 + k8l*8 + (lane&3);  n0 = nc*256 + wn*128 + ntp*16 + (lane>>2)
__global__ void k0_pack(const float* __restrict__ W) {
    int g = blockIdx.x * 256 + threadIdx.x;          // 0..65535
    int lane = g & 31;
    int ntp  = (g >> 5) & 7;
    int k8l  = (g >> 8) & 3;
    int wn   = (g >> 10) & 1;
    int nc   = (g >> 11) & 1;
    int kt   = g >> 12;
    int k  = kt * 32 + k8l * 8 + (lane & 3);
    int n0 = nc * 256 + wn * 128 + ntp * 16 + (lane >> 2);
    uint4 v;
    v.x = f2tf32(W[(size_t)k * FEAT + n0]);
    v.y = f2tf32(W[(size_t)(k + 4) * FEAT + n0]);
    v.z = f2tf32(W[(size_t)k * FEAT + n0 + 8]);
    v.w = f2tf32(W[(size_t)(k + 4) * FEAT + n0 + 8]);
    ((uint4*)g_Wfrag)[g] = v;
}

// ---------------- k1: pipelined tf32 mma GEMM + tanh + score + exp + pool ----------------
__device__ __forceinline__ void load_tile(uint32_t a_s, uint32_t b_s,
                                          const float* __restrict__ xg,
                                          int row0, int it, int tid) {
    const int nc = it >> 4;
    const int kt = it & 15;
    // A: x[row0..row0+127][kt*32..+32), 16B chunks, padded rows (144B)
    #pragma unroll
    for (int i = 0; i < 2; i++) {
        int id = tid + i * THREADS;
        int r = id >> 3, c = id & 7;
        cpa16(a_s + r * (ASTR * 4) + c * 16,
              xg + (size_t)(row0 + r) * FEAT + kt * 32 + c * 4);
    }
    // B: linear 32KB slab from g_Wfrag
    const char* src = (const char*)g_Wfrag + (size_t)(kt * 2 + nc) * B_TILE_B;
    #pragma unroll
    for (int i = 0; i < 4; i++) {
        int id = tid + i * THREADS;
        cpa16(b_s + id * 16, src + id * 16);
    }
    asm volatile("cp.async.commit_group;" ::: "memory");
}

__global__ __launch_bounds__(THREADS, 1)
void k1_gemm(const float* __restrict__ xg, const float* __restrict__ bg,
             const float* __restrict__ ug) {
    extern __shared__ char smem[];
    const uint32_t sbase = smem_u32(smem);
    const int tid  = threadIdx.x;
    const int lane = tid & 31;
    const int wid  = tid >> 5;
    const int wm   = wid & 7;        // 8 row groups of 16
    const int wn   = wid >> 3;       // 2 col groups of 128 (within 256-half)
    const int lr   = lane >> 2;
    const int lc   = lane & 3;
    const int row0 = blockIdx.x * M_CTA;

    float* usm  = (float*)(smem + OFF_U);
    float* bsm  = (float*)(smem + OFF_BV);
    float* sred = (float*)(smem + OFF_SRED);
    float* se_s = (float*)(smem + OFF_SE);

    usm[tid] = ug[tid];
    bsm[tid] = bg[tid];

    const uint32_t a_s[2] = { sbase + OFF_A0, sbase + OFF_A1 };
    const uint32_t b_s[2] = { sbase + OFF_B0, sbase + OFF_B1 };

    load_tile(a_s[0], b_s[0], xg, row0, 0, tid);
    load_tile(a_s[1], b_s[1], xg, row0, 1, tid);

    float sp0 = 0.0f, sp1 = 0.0f;

    for (int nc = 0; nc < NC; nc++) {
        float acc[16][4];
        #pragma unroll
        for (int nt = 0; nt < 16; nt++)
            acc[nt][0] = acc[nt][1] = acc[nt][2] = acc[nt][3] = 0.0f;

        for (int kt = 0; kt < NKT; kt++) {
            const int it = nc * NKT + kt;
            if (it < NC * NKT - 1)
                asm volatile("cp.async.wait_group 1;" ::: "memory");
            else
                asm volatile("cp.async.wait_group 0;" ::: "memory");
            __syncthreads();

            const float*  Af = (const float*)(smem + (( it & 1) ? OFF_A1 : OFF_A0));
            const float4* Bf = (const float4*)(smem + ((it & 1) ? OFF_B1 : OFF_B0));

            #pragma unroll
            for (int k8l = 0; k8l < 4; k8l++) {
                const int ca = k8l * 8 + lc;
                const int ra = (wm * 16 + lr) * ASTR;
                uint32_t a0 = __float_as_uint(Af[ra + ca]);
                uint32_t a1 = __float_as_uint(Af[ra + 8 * ASTR + ca]);
                uint32_t a2 = __float_as_uint(Af[ra + ca + 4]);
                uint32_t a3 = __float_as_uint(Af[ra + 8 * ASTR + ca + 4]);
                #pragma unroll
                for (int ntp = 0; ntp < 8; ntp++) {
                    float4 bb = Bf[((wn * 4 + k8l) * 8 + ntp) * 32 + lane];
                    mma_tf32(acc[2*ntp][0], acc[2*ntp][1], acc[2*ntp][2], acc[2*ntp][3],
                             a0, a1, a2, a3, __float_as_uint(bb.x), __float_as_uint(bb.y));
                    mma_tf32(acc[2*ntp+1][0], acc[2*ntp+1][1], acc[2*ntp+1][2], acc[2*ntp+1][3],
                             a0, a1, a2, a3, __float_as_uint(bb.z), __float_as_uint(bb.w));
                }
            }

            if (it + 2 < NC * NKT) {
                __syncthreads();   // everyone done reading buf[it&1]
                load_tile(a_s[it & 1], b_s[it & 1], xg, row0, it + 2, tid);
            }
        }

        // epilogue for this n-half: tanh + dot(u), fixed order
        #pragma unroll
        for (int nt = 0; nt < 16; nt++) {
            int n = nc * 256 + wn * 128 + nt * 8 + lc * 2;
            float u0 = usm[n], u1 = usm[n + 1];
            float b0 = bsm[n], b1 = bsm[n + 1];
            sp0 += ftanh(acc[nt][0] + b0) * u0;
            sp0 += ftanh(acc[nt][1] + b1) * u1;
            sp1 += ftanh(acc[nt][2] + b0) * u0;
            sp1 += ftanh(acc[nt][3] + b1) * u1;
        }
    }

    // reduce over 4 lanes sharing a row (fixed order)
    sp0 += __shfl_xor_sync(0xffffffffu, sp0, 1);
    sp0 += __shfl_xor_sync(0xffffffffu, sp0, 2);
    sp1 += __shfl_xor_sync(0xffffffffu, sp1, 1);
    sp1 += __shfl_xor_sync(0xffffffffu, sp1, 2);
    __syncthreads();
    if ((lane & 3) == 0) {
        int r = wm * 16 + lr;
        sred[wn * 128 + r]     = sp0;
        sred[wn * 128 + r + 8] = sp1;
    }
    __syncthreads();

    if (tid < M_CTA) {
        float s = sred[tid] + sred[128 + tid];
        float e = expf(s);
        se_s[tid] = e;
        sred[tid] = e;
    }
    __syncthreads();
    #pragma unroll
    for (int off = 64; off > 0; off >>= 1) {
        if (tid < off) sred[tid] += sred[tid + off];
        __syncthreads();
    }
    if (tid == 0) g_part[blockIdx.x] = sred[0];

    // pooling partial: po[f] = sum_r x[row0+r][f] * e[r]   (fixed order)
    {
        const float* xb = xg + (size_t)row0 * FEAT + tid;
        float a0 = 0.f, a1 = 0.f, a2 = 0.f, a3 = 0.f;
        #pragma unroll 4
        for (int r = 0; r < M_CTA; r += 4) {
            a0 += xb[(size_t)(r + 0) * FEAT] * se_s[r + 0];
            a1 += xb[(size_t)(r + 1) * FEAT] * se_s[r + 1];
            a2 += xb[(size_t)(r + 2) * FEAT] * se_s[r + 2];
            a3 += xb[(size_t)(r + 3) * FEAT] * se_s[r + 3];
        }
        g_po[(size_t)blockIdx.x * FEAT + tid] = (a0 + a1) + (a2 + a3);
    }
}

// ---------------- k2: reduce 512 partials ----------------
__global__ void k2_reduce() {
    __shared__ float red[512];
    int tid = threadIdx.x;
    red[tid] = g_part[tid];
    __syncthreads();
    #pragma unroll
    for (int off = 256; off > 0; off >>= 1) {
        if (tid < off) red[tid] += red[tid + off];
        __syncthreads();
    }
    if (tid == 0) g_sumE = red[0];
}

// ---------------- k4: combine + normalize ----------------
__global__ __launch_bounds__(512)
void k4_final(float* __restrict__ out) {
    int b = blockIdx.x, f = threadIdx.x;
    float s = 0.0f;
    #pragma unroll
    for (int c = 0; c < 32; c++)
        s += g_po[(size_t)(b * 32 + c) * FEAT + f];
    out[b * FEAT + f] = s / (g_sumE + 1e-7f);
}

extern "C" void kernel_launch(void* const* d_in, const int* in_sizes, int n_in,
                              void* d_out, int out_size) {
    const float* x = (const float*)d_in[0];
    const float* W = (const float*)d_in[1];
    const float* b = (const float*)d_in[2];
    const float* u = (const float*)d_in[3];
    float* out = (float*)d_out;

    cudaFuncSetAttribute(k1_gemm, cudaFuncAttributeMaxDynamicSharedMemorySize, SMEM_TOTAL);

    k0_pack<<<256, 256>>>(W);
    k1_gemm<<<NUM_CTAS, THREADS, SMEM_TOTAL>>>(x, b, u);
    k2_reduce<<<1, 512>>>();
    k4_final<<<BATCH, 512>>>(out);
}

// round 7
// speedup vs baseline: 1.8635x; 1.1028x over previous
#include <cuda_runtime.h>
#include <stdint.h>

// ---------------- problem constants ----------------
#define BATCH 16
#define SEQ   4096
#define FEAT  512
#define MROWS (BATCH*SEQ)          // 65536
#define M_CTA 128
#define NUM_CTAS (MROWS/M_CTA)     // 512
#define THREADS 512
#define NKT 16                     // K slices of 32
#define NC 2                       // N halves of 256

// A slice smem: 128 rows x (32+4 pad) words = 144B/row
#define ASTR 36
#define A_TILE_B (M_CTA*ASTR*4)    // 18432
#define B_TILE_B 32768             // 32 k x 256 n x 4B (fragment-major)

// smem layout (bytes)
#define OFF_U    0
#define OFF_BV   2048
#define OFF_SRED 4096              // 4*128 floats = 2048B
#define OFF_SE   6144              // 128 floats
#define OFF_A0   8192
#define OFF_A1   (OFF_A0 + A_TILE_B)   // 26624
#define OFF_B0   (OFF_A1 + A_TILE_B)   // 45056
#define OFF_B1   (OFF_B0 + B_TILE_B)   // 77824
#define SMEM_TOTAL (OFF_B1 + B_TILE_B) // 110592

// ---------------- global scratch ----------------
__device__ float g_Wfrag[FEAT*FEAT];      // fragment-major, tf32(RNA) W
__device__ float g_part[NUM_CTAS];
__device__ float g_sumE;
__device__ float g_po[(size_t)NUM_CTAS*FEAT];

__device__ __forceinline__ uint32_t f2tf32(float x) {
    uint32_t r;
    asm("cvt.rna.tf32.f32 %0, %1;" : "=r"(r) : "f"(x));
    return r;
}

__device__ __forceinline__ void mma_tf32(float& d0, float& d1, float& d2, float& d3,
                                         uint32_t a0, uint32_t a1, uint32_t a2, uint32_t a3,
                                         uint32_t b0, uint32_t b1) {
    asm volatile(
        "mma.sync.aligned.m16n8k8.row.col.f32.tf32.tf32.f32 "
        "{%0,%1,%2,%3}, {%4,%5,%6,%7}, {%8,%9}, {%0,%1,%2,%3};"
        : "+f"(d0), "+f"(d1), "+f"(d2), "+f"(d3)
        : "r"(a0), "r"(a1), "r"(a2), "r"(a3), "r"(b0), "r"(b1));
}

__device__ __forceinline__ uint32_t smem_u32(const void* p) {
    uint32_t a;
    asm("{ .reg .u64 t; cvta.to.shared.u64 t, %1; cvt.u32.u64 %0, t; }" : "=r"(a) : "l"(p));
    return a;
}

__device__ __forceinline__ void cpa16(uint32_t dst, const void* src) {
    asm volatile("cp.async.cg.shared.global [%0], [%1], 16;" :: "r"(dst), "l"(src));
}

// fast tanh via 2 MUFU; rel err ~1e-6, saturates to +-1
__device__ __forceinline__ float ftanh(float v) {
    float t = __expf(2.0f * v);
    return 1.0f - __fdividef(2.0f, t + 1.0f);
}

// ---------------- k0: pack W -> fragment-major tf32 ----------------
// float4 g[idx] with idx = ((kt*2+nc)*64 + k8l*16 + wn*4 + ntp)*32 + lane
// float4 = ( W[k][n0], W[k+4][n0], W[k][n0+8], W[k+4][n0+8] ) as RNA tf32 bits
// k  = kt*32 + k8l*8 + (lane&3)
// n0 = nc*256 + wn*64 + ntp*16 + (lane>>2)
__global__ void k0_pack(const float* __restrict__ W) {
    int g = blockIdx.x * 256 + threadIdx.x;          // 0..65535
    int lane = g & 31;
    int t    = g >> 5;
    int ntp  = t & 3;
    int wn   = (t >> 2) & 3;
    int k8l  = (t >> 4) & 3;
    int nc   = (t >> 6) & 1;
    int kt   = t >> 7;
    int k  = kt * 32 + k8l * 8 + (lane & 3);
    int n0 = nc * 256 + wn * 64 + ntp * 16 + (lane >> 2);
    uint4 v;
    v.x = f2tf32(W[(size_t)k * FEAT + n0]);
    v.y = f2tf32(W[(size_t)(k + 4) * FEAT + n0]);
    v.z = f2tf32(W[(size_t)k * FEAT + n0 + 8]);
    v.w = f2tf32(W[(size_t)(k + 4) * FEAT + n0 + 8]);
    ((uint4*)g_Wfrag)[g] = v;
}

// ---------------- k1: pipelined tf32 mma GEMM + tanh + score + exp + pool ----------------
__device__ __forceinline__ void load_tile(uint32_t a_s, uint32_t b_s,
                                          const float* __restrict__ xg,
                                          int row0, int it, int tid) {
    const int nc = it >> 4;
    const int kt = it & 15;
    // A: x[row0..row0+127][kt*32..+32), 16B chunks, padded rows (144B)
    #pragma unroll
    for (int i = 0; i < 2; i++) {
        int id = tid + i * THREADS;
        int r = id >> 3, c = id & 7;
        cpa16(a_s + r * (ASTR * 4) + c * 16,
              xg + (size_t)(row0 + r) * FEAT + kt * 32 + c * 4);
    }
    // B: linear 32KB slab from g_Wfrag
    const char* src = (const char*)g_Wfrag + (size_t)(kt * 2 + nc) * B_TILE_B;
    #pragma unroll
    for (int i = 0; i < 4; i++) {
        int id = tid + i * THREADS;
        cpa16(b_s + id * 16, src + id * 16);
    }
    asm volatile("cp.async.commit_group;" ::: "memory");
}

__global__ __launch_bounds__(THREADS, 1)
void k1_gemm(const float* __restrict__ xg, const float* __restrict__ bg,
             const float* __restrict__ ug) {
    extern __shared__ char smem[];
    const uint32_t sbase = smem_u32(smem);
    const int tid  = threadIdx.x;
    const int lane = tid & 31;
    const int wid  = tid >> 5;
    const int wm   = wid & 3;        // 4 row groups of 32
    const int wn   = wid >> 2;       // 4 col groups of 64 (within 256-half)
    const int lr   = lane >> 2;
    const int lc   = lane & 3;
    const int row0 = blockIdx.x * M_CTA;

    float* usm  = (float*)(smem + OFF_U);
    float* bsm  = (float*)(smem + OFF_BV);
    float* sred = (float*)(smem + OFF_SRED);
    float* se_s = (float*)(smem + OFF_SE);

    usm[tid] = ug[tid];
    bsm[tid] = bg[tid];

    const uint32_t a_s[2] = { sbase + OFF_A0, sbase + OFF_A1 };
    const uint32_t b_s[2] = { sbase + OFF_B0, sbase + OFF_B1 };

    load_tile(a_s[0], b_s[0], xg, row0, 0, tid);
    load_tile(a_s[1], b_s[1], xg, row0, 1, tid);

    // score partials: [mt][row-half]  (rows wm*32+mt*16+lr and +8)
    float sp[2][2] = {{0.f, 0.f}, {0.f, 0.f}};

    for (int nc = 0; nc < NC; nc++) {
        float acc[2][8][4];
        #pragma unroll
        for (int mt = 0; mt < 2; mt++)
            #pragma unroll
            for (int nt = 0; nt < 8; nt++)
                acc[mt][nt][0] = acc[mt][nt][1] = acc[mt][nt][2] = acc[mt][nt][3] = 0.0f;

        for (int kt = 0; kt < NKT; kt++) {
            const int it = nc * NKT + kt;
            if (it < NC * NKT - 1)
                asm volatile("cp.async.wait_group 1;" ::: "memory");
            else
                asm volatile("cp.async.wait_group 0;" ::: "memory");
            __syncthreads();

            const float*  Af = (const float*)(smem + (( it & 1) ? OFF_A1 : OFF_A0));
            const float4* Bf = (const float4*)(smem + ((it & 1) ? OFF_B1 : OFF_B0));

            #pragma unroll
            for (int k8l = 0; k8l < 4; k8l++) {
                const int ca = k8l * 8 + lc;
                uint32_t a[2][4];
                #pragma unroll
                for (int mt = 0; mt < 2; mt++) {
                    const int ra = (wm * 32 + mt * 16 + lr) * ASTR;
                    a[mt][0] = __float_as_uint(Af[ra + ca]);
                    a[mt][1] = __float_as_uint(Af[ra + 8 * ASTR + ca]);
                    a[mt][2] = __float_as_uint(Af[ra + ca + 4]);
                    a[mt][3] = __float_as_uint(Af[ra + 8 * ASTR + ca + 4]);
                }
                #pragma unroll
                for (int ntp = 0; ntp < 4; ntp++) {
                    float4 bb = Bf[(size_t)((k8l * 16 + wn * 4 + ntp) * 32 + lane)];
                    uint32_t b0 = __float_as_uint(bb.x), b1 = __float_as_uint(bb.y);
                    uint32_t b2 = __float_as_uint(bb.z), b3 = __float_as_uint(bb.w);
                    #pragma unroll
                    for (int mt = 0; mt < 2; mt++) {
                        mma_tf32(acc[mt][2*ntp][0], acc[mt][2*ntp][1],
                                 acc[mt][2*ntp][2], acc[mt][2*ntp][3],
                                 a[mt][0], a[mt][1], a[mt][2], a[mt][3], b0, b1);
                        mma_tf32(acc[mt][2*ntp+1][0], acc[mt][2*ntp+1][1],
                                 acc[mt][2*ntp+1][2], acc[mt][2*ntp+1][3],
                                 a[mt][0], a[mt][1], a[mt][2], a[mt][3], b2, b3);
                    }
                }
            }

            if (it + 2 < NC * NKT) {
                __syncthreads();   // everyone done reading buf[it&1]
                load_tile(a_s[it & 1], b_s[it & 1], xg, row0, it + 2, tid);
            }
        }

        // epilogue for this n-half: tanh + dot(u), fixed order
        #pragma unroll
        for (int mt = 0; mt < 2; mt++) {
            #pragma unroll
            for (int nt = 0; nt < 8; nt++) {
                int n = nc * 256 + wn * 64 + nt * 8 + lc * 2;
                float u0 = usm[n], u1 = usm[n + 1];
                float b0 = bsm[n], b1 = bsm[n + 1];
                sp[mt][0] += ftanh(acc[mt][nt][0] + b0) * u0;
                sp[mt][0] += ftanh(acc[mt][nt][1] + b1) * u1;
                sp[mt][1] += ftanh(acc[mt][nt][2] + b0) * u0;
                sp[mt][1] += ftanh(acc[mt][nt][3] + b1) * u1;
            }
        }
    }

    // reduce over 4 lanes sharing a row (fixed order)
    #pragma unroll
    for (int mt = 0; mt < 2; mt++) {
        #pragma unroll
        for (int h = 0; h < 2; h++) {
            sp[mt][h] += __shfl_xor_sync(0xffffffffu, sp[mt][h], 1);
            sp[mt][h] += __shfl_xor_sync(0xffffffffu, sp[mt][h], 2);
        }
    }
    __syncthreads();
    if ((lane & 3) == 0) {
        #pragma unroll
        for (int mt = 0; mt < 2; mt++) {
            int r = wm * 32 + mt * 16 + lr;
            sred[wn * 128 + r]     = sp[mt][0];
            sred[wn * 128 + r + 8] = sp[mt][1];
        }
    }
    __syncthreads();

    if (tid < M_CTA) {
        float s = (sred[tid] + sred[128 + tid]) + (sred[256 + tid] + sred[384 + tid]);
        float e = expf(s);
        se_s[tid] = e;
        sred[tid] = e;
    }
    __syncthreads();
    #pragma unroll
    for (int off = 64; off > 0; off >>= 1) {
        if (tid < off) sred[tid] += sred[tid + off];
        __syncthreads();
    }
    if (tid == 0) g_part[blockIdx.x] = sred[0];

    // pooling partial: po[f] = sum_r x[row0+r][f] * e[r]   (fixed order)
    {
        const float* xb = xg + (size_t)row0 * FEAT + tid;
        float a0 = 0.f, a1 = 0.f, a2 = 0.f, a3 = 0.f;
        #pragma unroll 4
        for (int r = 0; r < M_CTA; r += 4) {
            a0 += xb[(size_t)(r + 0) * FEAT] * se_s[r + 0];
            a1 += xb[(size_t)(r + 1) * FEAT] * se_s[r + 1];
            a2 += xb[(size_t)(r + 2) * FEAT] * se_s[r + 2];
            a3 += xb[(size_t)(r + 3) * FEAT] * se_s[r + 3];
        }
        g_po[(size_t)blockIdx.x * FEAT + tid] = (a0 + a1) + (a2 + a3);
    }
}

// ---------------- k2: reduce 512 partials ----------------
__global__ void k2_reduce() {
    __shared__ float red[512];
    int tid = threadIdx.x;
    red[tid] = g_part[tid];
    __syncthreads();
    #pragma unroll
    for (int off = 256; off > 0; off >>= 1) {
        if (tid < off) red[tid] += red[tid + off];
        __syncthreads();
    }
    if (tid == 0) g_sumE = red[0];
}

// ---------------- k4: combine + normalize ----------------
__global__ __launch_bounds__(512)
void k4_final(float* __restrict__ out) {
    int b = blockIdx.x, f = threadIdx.x;
    float s = 0.0f;
    #pragma unroll
    for (int c = 0; c < 32; c++)
        s += g_po[(size_t)(b * 32 + c) * FEAT + f];
    out[b * FEAT + f] = s / (g_sumE + 1e-7f);
}

extern "C" void kernel_launch(void* const* d_in, const int* in_sizes, int n_in,
                              void* d_out, int out_size) {
    const float* x = (const float*)d_in[0];
    const float* W = (const float*)d_in[1];
    const float* b = (const float*)d_in[2];
    const float* u = (const float*)d_in[3];
    float* out = (float*)d_out;

    cudaFuncSetAttribute(k1_gemm, cudaFuncAttributeMaxDynamicSharedMemorySize, SMEM_TOTAL);

    k0_pack<<<256, 256>>>(W);
    k1_gemm<<<NUM_CTAS, THREADS, SMEM_TOTAL>>>(x, b, u);
    k2_reduce<<<1, 512>>>();
    k4_final<<<BATCH, 512>>>(out);
}

// round 8
// speedup vs baseline: 2.2198x; 1.1912x over previous
#include <cuda_runtime.h>
#include <stdint.h>

// ---------------- problem constants ----------------
#define BATCH 16
#define SEQ   4096
#define FEAT  512
#define MROWS (BATCH*SEQ)          // 65536
#define M_CTA 64
#define NUM_CTAS (MROWS/M_CTA)     // 1024
#define THREADS 256
#define NKT 16                     // K slices of 32
#define NC 2                       // N halves of 256

// A slice smem: 64 rows x (32+4 pad) words = 144B/row
#define ASTR 36
#define A_TILE_B (M_CTA*ASTR*4)    // 9216
#define B_TILE_B 32768             // 32 k x 256 n x 4B (fragment-major)

// smem layout (bytes)
#define OFF_U    0                 // 2048
#define OFF_BV   2048              // 2048
#define OFF_SRED 4096              // 4*64 floats = 1024
#define OFF_SE   5120              // 64 floats = 256
#define OFF_A0   5632
#define OFF_A1   (OFF_A0 + A_TILE_B)   // 14848
#define OFF_B0   (OFF_A1 + A_TILE_B)   // 24064
#define OFF_B1   (OFF_B0 + B_TILE_B)   // 56832
#define SMEM_TOTAL (OFF_B1 + B_TILE_B) // 89600  (x2 CTAs = 179200 < 228KB)

// ---------------- global scratch ----------------
__device__ float g_Wfrag[FEAT*FEAT];      // fragment-major, tf32(RNA) W
__device__ float g_part[NUM_CTAS];
__device__ float g_sumE;
__device__ float g_po[(size_t)NUM_CTAS*FEAT];

__device__ __forceinline__ uint32_t f2tf32(float x) {
    uint32_t r;
    asm("cvt.rna.tf32.f32 %0, %1;" : "=r"(r) : "f"(x));
    return r;
}

__device__ __forceinline__ void mma_tf32(float& d0, float& d1, float& d2, float& d3,
                                         uint32_t a0, uint32_t a1, uint32_t a2, uint32_t a3,
                                         uint32_t b0, uint32_t b1) {
    asm volatile(
        "mma.sync.aligned.m16n8k8.row.col.f32.tf32.tf32.f32 "
        "{%0,%1,%2,%3}, {%4,%5,%6,%7}, {%8,%9}, {%0,%1,%2,%3};"
        : "+f"(d0), "+f"(d1), "+f"(d2), "+f"(d3)
        : "r"(a0), "r"(a1), "r"(a2), "r"(a3), "r"(b0), "r"(b1));
}

__device__ __forceinline__ void cpa16(uint32_t dst, const void* src) {
    asm volatile("cp.async.cg.shared.global [%0], [%1], 16;" :: "r"(dst), "l"(src));
}

__device__ __forceinline__ uint32_t smem_u32(const void* p) {
    uint32_t a;
    asm("{ .reg .u64 t; cvta.to.shared.u64 t, %1; cvt.u32.u64 %0, t; }" : "=r"(a) : "l"(p));
    return a;
}

// fast tanh via 2 MUFU; rel err ~1e-6, saturates to +-1
__device__ __forceinline__ float ftanh(float v) {
    float t = __expf(2.0f * v);
    return 1.0f - __fdividef(2.0f, t + 1.0f);
}

// ---------------- k0: pack W -> fragment-major tf32 (unchanged layout) ----------------
// float4 g[idx] with idx = ((kt*2+nc)*64 + k8l*16 + wn*4 + ntp)*32 + lane
// float4 = ( W[k][n0], W[k+4][n0], W[k][n0+8], W[k+4][n0+8] ) as RNA tf32 bits
// k  = kt*32 + k8l*8 + (lane&3)
// n0 = nc*256 + wn*64 + ntp*16 + (lane>>2)
__global__ void k0_pack(const float* __restrict__ W) {
    int g = blockIdx.x * 256 + threadIdx.x;          // 0..65535
    int lane = g & 31;
    int t    = g >> 5;
    int ntp  = t & 3;
    int wn   = (t >> 2) & 3;
    int k8l  = (t >> 4) & 3;
    int nc   = (t >> 6) & 1;
    int kt   = t >> 7;
    int k  = kt * 32 + k8l * 8 + (lane & 3);
    int n0 = nc * 256 + wn * 64 + ntp * 16 + (lane >> 2);
    uint4 v;
    v.x = f2tf32(W[(size_t)k * FEAT + n0]);
    v.y = f2tf32(W[(size_t)(k + 4) * FEAT + n0]);
    v.z = f2tf32(W[(size_t)k * FEAT + n0 + 8]);
    v.w = f2tf32(W[(size_t)(k + 4) * FEAT + n0 + 8]);
    ((uint4*)g_Wfrag)[g] = v;
}

// ---------------- k1: pipelined tf32 mma GEMM + tanh + score + exp + pool ----------------
__device__ __forceinline__ void load_tile(uint32_t a_s, uint32_t b_s,
                                          const float* __restrict__ xg,
                                          int row0, int it, int tid) {
    const int nc = it >> 4;
    const int kt = it & 15;
    // A: x[row0..row0+63][kt*32..+32), 16B chunks, padded rows (144B)
    #pragma unroll
    for (int i = 0; i < 2; i++) {
        int id = tid + i * THREADS;       // 512 chunks
        int r = id >> 3, c = id & 7;
        cpa16(a_s + r * (ASTR * 4) + c * 16,
              xg + (size_t)(row0 + r) * FEAT + kt * 32 + c * 4);
    }
    // B: linear 32KB slab from g_Wfrag
    const char* src = (const char*)g_Wfrag + (size_t)(kt * 2 + nc) * B_TILE_B;
    #pragma unroll
    for (int i = 0; i < 8; i++) {
        int id = tid + i * THREADS;       // 2048 chunks
        cpa16(b_s + id * 16, src + id * 16);
    }
    asm volatile("cp.async.commit_group;" ::: "memory");
}

__global__ __launch_bounds__(THREADS, 2)
void k1_gemm(const float* __restrict__ xg, const float* __restrict__ bg,
             const float* __restrict__ ug) {
    extern __shared__ char smem[];
    const uint32_t sbase = smem_u32(smem);
    const int tid  = threadIdx.x;
    const int lane = tid & 31;
    const int wid  = tid >> 5;
    const int wm   = wid & 1;        // 2 row groups of 32
    const int wn   = wid >> 1;       // 4 col groups of 64 (within 256-half)
    const int lr   = lane >> 2;
    const int lc   = lane & 3;
    const int row0 = blockIdx.x * M_CTA;

    float* usm  = (float*)(smem + OFF_U);
    float* bsm  = (float*)(smem + OFF_BV);
    float* sred = (float*)(smem + OFF_SRED);
    float* se_s = (float*)(smem + OFF_SE);

    #pragma unroll
    for (int i = 0; i < 2; i++) {
        usm[tid + i * THREADS] = ug[tid + i * THREADS];
        bsm[tid + i * THREADS] = bg[tid + i * THREADS];
    }

    const uint32_t a_s[2] = { sbase + OFF_A0, sbase + OFF_A1 };
    const uint32_t b_s[2] = { sbase + OFF_B0, sbase + OFF_B1 };

    load_tile(a_s[0], b_s[0], xg, row0, 0, tid);
    load_tile(a_s[1], b_s[1], xg, row0, 1, tid);

    // score partials: [mt][row-half]  (rows wm*32+mt*16+lr and +8)
    float sp[2][2] = {{0.f, 0.f}, {0.f, 0.f}};

    for (int nc = 0; nc < NC; nc++) {
        float acc[2][8][4];
        #pragma unroll
        for (int mt = 0; mt < 2; mt++)
            #pragma unroll
            for (int nt = 0; nt < 8; nt++)
                acc[mt][nt][0] = acc[mt][nt][1] = acc[mt][nt][2] = acc[mt][nt][3] = 0.0f;

        for (int kt = 0; kt < NKT; kt++) {
            const int it = nc * NKT + kt;
            if (it < NC * NKT - 1)
                asm volatile("cp.async.wait_group 1;" ::: "memory");
            else
                asm volatile("cp.async.wait_group 0;" ::: "memory");
            __syncthreads();

            const float*  Af = (const float*)(smem + (( it & 1) ? OFF_A1 : OFF_A0));
            const float4* Bf = (const float4*)(smem + ((it & 1) ? OFF_B1 : OFF_B0));

            #pragma unroll
            for (int k8l = 0; k8l < 4; k8l++) {
                const int ca = k8l * 8 + lc;
                uint32_t a[2][4];
                #pragma unroll
                for (int mt = 0; mt < 2; mt++) {
                    const int ra = (wm * 32 + mt * 16 + lr) * ASTR;
                    a[mt][0] = __float_as_uint(Af[ra + ca]);
                    a[mt][1] = __float_as_uint(Af[ra + 8 * ASTR + ca]);
                    a[mt][2] = __float_as_uint(Af[ra + ca + 4]);
                    a[mt][3] = __float_as_uint(Af[ra + 8 * ASTR + ca + 4]);
                }
                #pragma unroll
                for (int ntp = 0; ntp < 4; ntp++) {
                    float4 bb = Bf[(size_t)((k8l * 16 + wn * 4 + ntp) * 32 + lane)];
                    uint32_t b0 = __float_as_uint(bb.x), b1 = __float_as_uint(bb.y);
                    uint32_t b2 = __float_as_uint(bb.z), b3 = __float_as_uint(bb.w);
                    #pragma unroll
                    for (int mt = 0; mt < 2; mt++) {
                        mma_tf32(acc[mt][2*ntp][0], acc[mt][2*ntp][1],
                                 acc[mt][2*ntp][2], acc[mt][2*ntp][3],
                                 a[mt][0], a[mt][1], a[mt][2], a[mt][3], b0, b1);
                        mma_tf32(acc[mt][2*ntp+1][0], acc[mt][2*ntp+1][1],
                                 acc[mt][2*ntp+1][2], acc[mt][2*ntp+1][3],
                                 a[mt][0], a[mt][1], a[mt][2], a[mt][3], b2, b3);
                    }
                }
            }

            if (it + 2 < NC * NKT) {
                __syncthreads();   // everyone done reading buf[it&1]
                load_tile(a_s[it & 1], b_s[it & 1], xg, row0, it + 2, tid);
            }
        }

        // epilogue for this n-half: tanh + dot(u), fixed order
        #pragma unroll
        for (int mt = 0; mt < 2; mt++) {
            #pragma unroll
            for (int nt = 0; nt < 8; nt++) {
                int n = nc * 256 + wn * 64 + nt * 8 + lc * 2;
                float u0 = usm[n], u1 = usm[n + 1];
                float b0 = bsm[n], b1 = bsm[n + 1];
                sp[mt][0] += ftanh(acc[mt][nt][0] + b0) * u0;
                sp[mt][0] += ftanh(acc[mt][nt][1] + b1) * u1;
                sp[mt][1] += ftanh(acc[mt][nt][2] + b0) * u0;
                sp[mt][1] += ftanh(acc[mt][nt][3] + b1) * u1;
            }
        }
    }

    // reduce over 4 lanes sharing a row (fixed order)
    #pragma unroll
    for (int mt = 0; mt < 2; mt++) {
        #pragma unroll
        for (int h = 0; h < 2; h++) {
            sp[mt][h] += __shfl_xor_sync(0xffffffffu, sp[mt][h], 1);
            sp[mt][h] += __shfl_xor_sync(0xffffffffu, sp[mt][h], 2);
        }
    }
    __syncthreads();
    if ((lane & 3) == 0) {
        #pragma unroll
        for (int mt = 0; mt < 2; mt++) {
            int r = wm * 32 + mt * 16 + lr;
            sred[wn * 64 + r]     = sp[mt][0];
            sred[wn * 64 + r + 8] = sp[mt][1];
        }
    }
    __syncthreads();

    if (tid < M_CTA) {
        float s = (sred[tid] + sred[64 + tid]) + (sred[128 + tid] + sred[192 + tid]);
        float e = expf(s);
        se_s[tid] = e;
        sred[tid] = e;
    }
    __syncthreads();
    #pragma unroll
    for (int off = 32; off > 0; off >>= 1) {
        if (tid < off) sred[tid] += sred[tid + off];
        __syncthreads();
    }
    if (tid == 0) g_part[blockIdx.x] = sred[0];

    // pooling partial: po[f] = sum_r x[row0+r][f] * e[r]   (fixed order)
    // 256 threads cover 512 features: f = tid and tid+256
    {
        const float* xb = xg + (size_t)row0 * FEAT;
        float p0 = 0.f, p1 = 0.f;
        #pragma unroll 4
        for (int r = 0; r < M_CTA; r++) {
            float ev = se_s[r];
            p0 += xb[(size_t)r * FEAT + tid]       * ev;
            p1 += xb[(size_t)r * FEAT + tid + 256] * ev;
        }
        g_po[(size_t)blockIdx.x * FEAT + tid]       = p0;
        g_po[(size_t)blockIdx.x * FEAT + tid + 256] = p1;
    }
}

// ---------------- k2: reduce 1024 partials ----------------
__global__ void k2_reduce() {
    __shared__ float red[512];
    int tid = threadIdx.x;
    red[tid] = g_part[tid] + g_part[tid + 512];
    __syncthreads();
    #pragma unroll
    for (int off = 256; off > 0; off >>= 1) {
        if (tid < off) red[tid] += red[tid + off];
        __syncthreads();
    }
    if (tid == 0) g_sumE = red[0];
}

// ---------------- k4: combine 64 CTA partials per batch + normalize ----------------
__global__ __launch_bounds__(512)
void k4_final(float* __restrict__ out) {
    int b = blockIdx.x, f = threadIdx.x;
    float s = 0.0f;
    #pragma unroll
    for (int c = 0; c < 64; c++)
        s += g_po[(size_t)(b * 64 + c) * FEAT + f];
    out[b * FEAT + f] = s / (g_sumE + 1e-7f);
}

extern "C" void kernel_launch(void* const* d_in, const int* in_sizes, int n_in,
                              void* d_out, int out_size) {
    const float* x = (const float*)d_in[0];
    const float* W = (const float*)d_in[1];
    const float* b = (const float*)d_in[2];
    const float* u = (const float*)d_in[3];
    float* out = (float*)d_out;

    cudaFuncSetAttribute(k1_gemm, cudaFuncAttributeMaxDynamicSharedMemorySize, SMEM_TOTAL);

    k0_pack<<<256, 256>>>(W);
    k1_gemm<<<NUM_CTAS, THREADS, SMEM_TOTAL>>>(x, b, u);
    k2_reduce<<<1, 512>>>();
    k4_final<<<BATCH, 512>>>(out);
}